// round 2
// baseline (speedup 1.0000x reference)
#include <cuda_runtime.h>
#include <cstdint>

// Problem constants (fixed shapes from reference)
#define NN 50000          // nodes
#define NE 800000         // edges
#define D  128            // node feature dim
#define DE 16             // edge feature dim
#define HH 128            // hidden
#define DM 128            // message dim
#define K1 272            // 2*D + DE
#define KN 256            // D + DM

#define TE 128            // edge/node rows per block
#define HS_STRIDE 132     // padded stride for Hs [k][r]

// agg scratch: per-node aggregated messages
__device__ float g_agg[NN * DM];

// ---------------------------------------------------------------------------
// helpers
// ---------------------------------------------------------------------------
__device__ __forceinline__ float siluf(float x) {
    return x / (1.0f + __expf(-x));
}
__device__ __forceinline__ float sigmoidf_(float x) {
    return 1.0f / (1.0f + __expf(-x));
}
__device__ __forceinline__ uint64_t pack2(float lo, float hi) {
    uint64_t r;
    asm("mov.b64 %0, {%1, %2};" : "=l"(r) : "f"(lo), "f"(hi));
    return r;
}
__device__ __forceinline__ void unpack2(uint64_t v, float& lo, float& hi) {
    asm("mov.b64 {%0, %1}, %2;" : "=f"(lo), "=f"(hi) : "l"(v));
}
// packed dual fp32 FMA: d = a*b + d (lane-wise)
__device__ __forceinline__ void ffma2(uint64_t& d, uint64_t a, uint64_t b) {
    asm("fma.rn.f32x2 %0, %1, %2, %0;" : "+l"(d) : "l"(a), "l"(b));
}

// shared memory layout (floats):
//   Xs  [16*128]          k-major chunk of X^T
//   Ws  [16*128]          k-major chunk of W
//   Hs  [128*HS_STRIDE]   k-major intermediate (h, then m)
//   Wis [128]             gate weight
//   gates [128]
//   starts/ends [128+128] (ints)
#define SM_XS   0
#define SM_WS   (16*128)
#define SM_HS   (2*16*128)
#define SM_WIS  (SM_HS + 128*HS_STRIDE)
#define SM_GATE (SM_WIS + 128)
#define SM_IDX  (SM_GATE + 128)
#define SMEM_FLOATS (SM_IDX + 256)
#define SMEM_BYTES (SMEM_FLOATS * 4)

// 8x8 micro-tile GEMM inner step over one 16-deep k chunk.
// Xsrc: k-major [k][row] with stride xstride; Ws: [k][col] stride 128.
__device__ __forceinline__ void mma_chunk(const float* __restrict__ Xsrc, int xstride,
                                          const float* __restrict__ Ws,
                                          int tr, int tc, uint64_t acc[32]) {
#pragma unroll
    for (int k = 0; k < 16; k++) {
        const float* xrow = Xsrc + k * xstride + tr * 8;
        float4 a0 = *(const float4*)(xrow);
        float4 a1 = *(const float4*)(xrow + 4);
        const float* wrow = Ws + k * 128 + tc * 8;
        uint64_t b0 = *(const uint64_t*)(wrow + 0);
        uint64_t b1 = *(const uint64_t*)(wrow + 2);
        uint64_t b2 = *(const uint64_t*)(wrow + 4);
        uint64_t b3 = *(const uint64_t*)(wrow + 6);
        float av[8] = {a0.x, a0.y, a0.z, a0.w, a1.x, a1.y, a1.z, a1.w};
#pragma unroll
        for (int i = 0; i < 8; i++) {
            uint64_t ap = pack2(av[i], av[i]);
            ffma2(acc[i * 4 + 0], ap, b0);
            ffma2(acc[i * 4 + 1], ap, b1);
            ffma2(acc[i * 4 + 2], ap, b2);
            ffma2(acc[i * 4 + 3], ap, b3);
        }
    }
}

// load a 16x128 chunk of W (row-major [K][128]) into Ws
__device__ __forceinline__ void load_w_chunk(float* __restrict__ Ws,
                                             const float* __restrict__ W,
                                             int k0, int tid) {
#pragma unroll
    for (int it = 0; it < 2; it++) {
        int idx = tid + it * 256;          // 0..511
        int k = idx >> 5;                  // 0..15
        int j = (idx & 31) * 4;            // 0..124
        float4 v = *(const float4*)(W + (size_t)(k0 + k) * 128 + j);
        *(float4*)(Ws + k * 128 + j) = v;
    }
}

// ---------------------------------------------------------------------------
// Edge kernel: gather -> MLP(272->128 silu ->128) -> gate -> gated atomic scatter
// ---------------------------------------------------------------------------
__global__ void __launch_bounds__(256, 2)
edge_kernel(const float* __restrict__ nf, const int* __restrict__ ei,
            const float* __restrict__ ef,
            const float* __restrict__ We1, const float* __restrict__ be1,
            const float* __restrict__ We2, const float* __restrict__ be2,
            const float* __restrict__ Wi, const float* __restrict__ bi,
            float* __restrict__ agg) {
    extern __shared__ float sm[];
    float* Xs = sm + SM_XS;
    float* Ws = sm + SM_WS;
    float* Hs = sm + SM_HS;
    float* Wis = sm + SM_WIS;
    float* gates = sm + SM_GATE;
    int* starts = (int*)(sm + SM_IDX);
    int* ends = starts + 128;

    const int tid = threadIdx.x;
    const int e0 = blockIdx.x * TE;
    const int tc = tid & 15;
    const int tr = tid >> 4;

    if (tid < 128) {
        starts[tid] = ei[e0 + tid];
        ends[tid]   = ei[NE + e0 + tid];
        Wis[tid]    = Wi[tid];
    }

    uint64_t acc[32];
#pragma unroll
    for (int i = 0; i < 32; i++) acc[i] = 0ull;

    // ---- GEMM1: h = silu(X @ We1 + be1), K = 272 (17 chunks) ----
    for (int kc = 0; kc < 17; kc++) {
        int k0 = kc * 16;
        __syncthreads();
        // gather X chunk (k-major into Xs)
#pragma unroll
        for (int it = 0; it < 2; it++) {
            int idx = tid + it * 256;   // 0..511
            int e = idx & 127;
            int q = idx >> 7;           // 0..3
            int kl = q * 4;
            int kg = k0 + kl;
            const float* src;
            if (kg < 128)      src = nf + (size_t)starts[e] * D + kg;
            else if (kg < 256) src = nf + (size_t)ends[e] * D + (kg - 128);
            else               src = ef + (size_t)(e0 + e) * DE + (kg - 256);
            float4 v = *(const float4*)src;
            Xs[(kl + 0) * 128 + e] = v.x;
            Xs[(kl + 1) * 128 + e] = v.y;
            Xs[(kl + 2) * 128 + e] = v.z;
            Xs[(kl + 3) * 128 + e] = v.w;
        }
        load_w_chunk(Ws, We1, k0, tid);
        __syncthreads();
        mma_chunk(Xs, 128, Ws, tr, tc, acc);
    }

    // epilogue 1: bias + silu, stage h^T into Hs[c][r]
    {
        float b[8];
#pragma unroll
        for (int j = 0; j < 8; j++) b[j] = be1[tc * 8 + j];
        __syncthreads();
#pragma unroll
        for (int i = 0; i < 8; i++) {
            int r = tr * 8 + i;
#pragma unroll
            for (int jp = 0; jp < 4; jp++) {
                float lo, hi;
                unpack2(acc[i * 4 + jp], lo, hi);
                int c = tc * 8 + jp * 2;
                Hs[(c + 0) * HS_STRIDE + r] = siluf(lo + b[2 * jp]);
                Hs[(c + 1) * HS_STRIDE + r] = siluf(hi + b[2 * jp + 1]);
            }
        }
    }

#pragma unroll
    for (int i = 0; i < 32; i++) acc[i] = 0ull;

    // ---- GEMM2: m = h @ We2 + be2, K = 128 (8 chunks) ----
    for (int kc = 0; kc < 8; kc++) {
        int k0 = kc * 16;
        __syncthreads();
        load_w_chunk(Ws, We2, k0, tid);
        __syncthreads();
        mma_chunk(Hs + k0 * HS_STRIDE, HS_STRIDE, Ws, tr, tc, acc);
    }

    // epilogue 2: bias, stage m^T into Hs[c][r] (overwrite h)
    {
        float b[8];
#pragma unroll
        for (int j = 0; j < 8; j++) b[j] = be2[tc * 8 + j];
        __syncthreads();  // everyone done reading Hs
#pragma unroll
        for (int i = 0; i < 8; i++) {
            int r = tr * 8 + i;
#pragma unroll
            for (int jp = 0; jp < 4; jp++) {
                float lo, hi;
                unpack2(acc[i * 4 + jp], lo, hi);
                int c = tc * 8 + jp * 2;
                Hs[(c + 0) * HS_STRIDE + r] = lo + b[2 * jp];
                Hs[(c + 1) * HS_STRIDE + r] = hi + b[2 * jp + 1];
            }
        }
    }
    __syncthreads();

    // gate: sigmoid(m . Wi + bi), one thread per edge row
    if (tid < 128) {
        float s = 0.0f;
#pragma unroll 8
        for (int c = 0; c < 128; c++) s += Hs[c * HS_STRIDE + tid] * Wis[c];
        gates[tid] = sigmoidf_(s + bi[0]);
    }
    __syncthreads();

    // gated atomic scatter: agg[start[r], :] += m[r, :] * gate[r]
    {
        int r = tid & 127;
        int cbase = (tid >> 7) * 64;
        float g = gates[r];
        float* dst = agg + (size_t)starts[r] * DM + cbase;
#pragma unroll 8
        for (int c = 0; c < 64; c++) {
            atomicAdd(dst + c, Hs[(cbase + c) * HS_STRIDE + r] * g);
        }
    }
}

// ---------------------------------------------------------------------------
// Node kernel: y=[nf|agg] -> silu(y@Wn1+bn1)@Wn2+bn2 + residual
// ---------------------------------------------------------------------------
__global__ void __launch_bounds__(256, 2)
node_kernel(const float* __restrict__ nf, const float* __restrict__ agg,
            const float* __restrict__ Wn1, const float* __restrict__ bn1,
            const float* __restrict__ Wn2, const float* __restrict__ bn2,
            float* __restrict__ out) {
    extern __shared__ float sm[];
    float* Xs = sm + SM_XS;
    float* Ws = sm + SM_WS;
    float* Hs = sm + SM_HS;

    const int tid = threadIdx.x;
    const int n0 = blockIdx.x * TE;
    const int tc = tid & 15;
    const int tr = tid >> 4;

    uint64_t acc[32];
#pragma unroll
    for (int i = 0; i < 32; i++) acc[i] = 0ull;

    // ---- GEMM1: K = 256 (16 chunks) ----
    for (int kc = 0; kc < 16; kc++) {
        int k0 = kc * 16;
        __syncthreads();
#pragma unroll
        for (int it = 0; it < 2; it++) {
            int idx = tid + it * 256;
            int e = idx & 127;
            int q = idx >> 7;
            int kl = q * 4;
            int kg = k0 + kl;
            int n = n0 + e;
            if (n >= NN) n = NN - 1;
            const float* src = (kg < 128) ? (nf + (size_t)n * D + kg)
                                          : (agg + (size_t)n * DM + (kg - 128));
            float4 v = *(const float4*)src;
            Xs[(kl + 0) * 128 + e] = v.x;
            Xs[(kl + 1) * 128 + e] = v.y;
            Xs[(kl + 2) * 128 + e] = v.z;
            Xs[(kl + 3) * 128 + e] = v.w;
        }
        load_w_chunk(Ws, Wn1, k0, tid);
        __syncthreads();
        mma_chunk(Xs, 128, Ws, tr, tc, acc);
    }

    // epilogue: silu, stage into Hs[c][r]
    {
        float b[8];
#pragma unroll
        for (int j = 0; j < 8; j++) b[j] = bn1[tc * 8 + j];
        __syncthreads();
#pragma unroll
        for (int i = 0; i < 8; i++) {
            int r = tr * 8 + i;
#pragma unroll
            for (int jp = 0; jp < 4; jp++) {
                float lo, hi;
                unpack2(acc[i * 4 + jp], lo, hi);
                int c = tc * 8 + jp * 2;
                Hs[(c + 0) * HS_STRIDE + r] = siluf(lo + b[2 * jp]);
                Hs[(c + 1) * HS_STRIDE + r] = siluf(hi + b[2 * jp + 1]);
            }
        }
    }

#pragma unroll
    for (int i = 0; i < 32; i++) acc[i] = 0ull;

    // ---- GEMM2: K = 128 (8 chunks) ----
    for (int kc = 0; kc < 8; kc++) {
        int k0 = kc * 16;
        __syncthreads();
        load_w_chunk(Ws, Wn2, k0, tid);
        __syncthreads();
        mma_chunk(Hs + k0 * HS_STRIDE, HS_STRIDE, Ws, tr, tc, acc);
    }

    // epilogue: bias + residual, write out
    {
        float b[8];
#pragma unroll
        for (int j = 0; j < 8; j++) b[j] = bn2[tc * 8 + j];
#pragma unroll
        for (int i = 0; i < 8; i++) {
            int r = tr * 8 + i;
            int n = n0 + r;
            if (n >= NN) continue;
#pragma unroll
            for (int jp = 0; jp < 4; jp++) {
                float lo, hi;
                unpack2(acc[i * 4 + jp], lo, hi);
                int c = tc * 8 + jp * 2;
                float2 res = *(const float2*)(nf + (size_t)n * D + c);
                float2 o;
                o.x = res.x + lo + b[2 * jp];
                o.y = res.y + hi + b[2 * jp + 1];
                *(float2*)(out + (size_t)n * D + c) = o;
            }
        }
    }
}

// ---------------------------------------------------------------------------
// Passthrough: edge_indices must be VALUE-cast int -> float (output dtype is
// float32), not bit-copied.
// ---------------------------------------------------------------------------
__global__ void idx_to_float_kernel(const int* __restrict__ ei,
                                    float* __restrict__ out) {
    int i = blockIdx.x * blockDim.x + threadIdx.x;
    if (i < 2 * NE) out[i] = (float)ei[i];
}

// ---------------------------------------------------------------------------
extern "C" void kernel_launch(void* const* d_in, const int* in_sizes, int n_in,
                              void* d_out, int out_size) {
    const float* nf  = (const float*)d_in[0];
    const int*   ei  = (const int*)d_in[1];
    const float* ef  = (const float*)d_in[2];
    const float* We1 = (const float*)d_in[3];
    const float* be1 = (const float*)d_in[4];
    const float* We2 = (const float*)d_in[5];
    const float* be2 = (const float*)d_in[6];
    const float* Wi  = (const float*)d_in[7];
    const float* bi  = (const float*)d_in[8];
    const float* Wn1 = (const float*)d_in[9];
    const float* bn1 = (const float*)d_in[10];
    const float* Wn2 = (const float*)d_in[11];
    const float* bn2 = (const float*)d_in[12];
    float* out = (float*)d_out;

    cudaFuncSetAttribute(edge_kernel, cudaFuncAttributeMaxDynamicSharedMemorySize, SMEM_BYTES);
    cudaFuncSetAttribute(node_kernel, cudaFuncAttributeMaxDynamicSharedMemorySize, SMEM_BYTES);

    void* aggp = nullptr;
    cudaGetSymbolAddress(&aggp, g_agg);
    cudaMemsetAsync(aggp, 0, (size_t)NN * DM * sizeof(float));

    edge_kernel<<<NE / TE, 256, SMEM_BYTES>>>(nf, ei, ef, We1, be1, We2, be2,
                                              Wi, bi, (float*)aggp);
    node_kernel<<<(NN + TE - 1) / TE, 256, SMEM_BYTES>>>(nf, (const float*)aggp,
                                                         Wn1, bn1, Wn2, bn2, out);

    // passthrough outputs: edge_indices (value-cast to float), then edge_features
    idx_to_float_kernel<<<(2 * NE + 255) / 256, 256>>>(ei, out + (size_t)NN * D);
    cudaMemcpyAsync(out + (size_t)NN * D + 2ull * NE, d_in[2],
                    (size_t)NE * DE * sizeof(float), cudaMemcpyDeviceToDevice);
}

// round 3
// speedup vs baseline: 1.1530x; 1.1530x over previous
#include <cuda_runtime.h>
#include <cstdint>

// Problem constants (fixed shapes from reference)
#define NN 50000          // nodes
#define NE 800000         // edges
#define D  128            // node feature dim
#define DE 16             // edge feature dim
#define HH 128            // hidden
#define DM 128            // message dim

#define TE 128            // edge/node rows per block
#define HS_STRIDE 132     // padded stride for Hs [k][r] (must stay %4==0 for float4 loads)

// agg scratch: per-node aggregated messages
__device__ float g_agg[NN * DM];

// ---------------------------------------------------------------------------
// helpers
// ---------------------------------------------------------------------------
__device__ __forceinline__ float siluf(float x) {
    return x / (1.0f + __expf(-x));
}
__device__ __forceinline__ float sigmoidf_(float x) {
    return 1.0f / (1.0f + __expf(-x));
}
__device__ __forceinline__ uint64_t pack2(float lo, float hi) {
    uint64_t r;
    asm("mov.b64 %0, {%1, %2};" : "=l"(r) : "f"(lo), "f"(hi));
    return r;
}
__device__ __forceinline__ void unpack2(uint64_t v, float& lo, float& hi) {
    asm("mov.b64 {%0, %1}, %2;" : "=f"(lo), "=f"(hi) : "l"(v));
}
// packed dual fp32 FMA: d = a*b + d (lane-wise)
__device__ __forceinline__ void ffma2(uint64_t& d, uint64_t a, uint64_t b) {
    asm("fma.rn.f32x2 %0, %1, %2, %0;" : "+l"(d) : "l"(a), "l"(b));
}

// shared memory layout (floats)
#define SM_XS   0
#define SM_WS   (16*128)
#define SM_HS   (2*16*128)
#define SM_WIS  (SM_HS + 128*HS_STRIDE)
#define SM_GATE (SM_WIS + 128)
#define SM_IDX  (SM_GATE + 128)
#define SMEM_FLOATS (SM_IDX + 256)
#define SMEM_BYTES (SMEM_FLOATS * 4)

// 8x8 micro-tile GEMM inner step over one 16-deep k chunk.
// Xsrc: k-major [k][row] with stride xstride (rows tr*8..+7, broadcast across tc).
// Ws: [k][col] stride 128. Thread owns cols {tc*4..+3} and {64+tc*4..+3}:
// both loaded as LDS.128 with warp-contiguous addresses -> conflict-free.
__device__ __forceinline__ void mma_chunk(const float* __restrict__ Xsrc, int xstride,
                                          const float* __restrict__ Ws,
                                          int tr, int tc, uint64_t acc[32]) {
#pragma unroll
    for (int k = 0; k < 16; k++) {
        const float* xrow = Xsrc + k * xstride + tr * 8;
        float4 a0 = *(const float4*)(xrow);
        float4 a1 = *(const float4*)(xrow + 4);
        const float* wrow = Ws + k * 128 + tc * 4;
        ulonglong2 w0 = *(const ulonglong2*)(wrow);       // cols tc*4   .. tc*4+3
        ulonglong2 w1 = *(const ulonglong2*)(wrow + 64);  // cols 64+tc*4.. +3
        uint64_t b0 = w0.x, b1 = w0.y, b2 = w1.x, b3 = w1.y;
        float av[8] = {a0.x, a0.y, a0.z, a0.w, a1.x, a1.y, a1.z, a1.w};
#pragma unroll
        for (int i = 0; i < 8; i++) {
            uint64_t ap = pack2(av[i], av[i]);
            ffma2(acc[i * 4 + 0], ap, b0);
            ffma2(acc[i * 4 + 1], ap, b1);
            ffma2(acc[i * 4 + 2], ap, b2);
            ffma2(acc[i * 4 + 3], ap, b3);
        }
    }
}

// column base for acc pair jp (pair covers cols cbase, cbase+1)
__device__ __forceinline__ int col_base(int tc, int jp) {
    return (jp < 2) ? (tc * 4 + jp * 2) : (64 + tc * 4 + (jp - 2) * 2);
}

// load a 16x128 chunk of W (row-major [K][128]) into Ws
__device__ __forceinline__ void load_w_chunk(float* __restrict__ Ws,
                                             const float* __restrict__ W,
                                             int k0, int tid) {
#pragma unroll
    for (int it = 0; it < 2; it++) {
        int idx = tid + it * 256;          // 0..511
        int k = idx >> 5;                  // 0..15
        int j = (idx & 31) * 4;            // 0..124
        float4 v = *(const float4*)(W + (size_t)(k0 + k) * 128 + j);
        *(float4*)(Ws + k * 128 + j) = v;
    }
}

// ---------------------------------------------------------------------------
// Edge kernel: gather -> MLP(272->128 silu ->128) -> gate -> gated atomic scatter
// ---------------------------------------------------------------------------
__global__ void __launch_bounds__(256, 2)
edge_kernel(const float* __restrict__ nf, const int* __restrict__ ei,
            const float* __restrict__ ef,
            const float* __restrict__ We1, const float* __restrict__ be1,
            const float* __restrict__ We2, const float* __restrict__ be2,
            const float* __restrict__ Wi, const float* __restrict__ bi,
            float* __restrict__ agg) {
    extern __shared__ float sm[];
    float* Xs = sm + SM_XS;
    float* Ws = sm + SM_WS;
    float* Hs = sm + SM_HS;
    float* Wis = sm + SM_WIS;
    float* gates = sm + SM_GATE;
    int* starts = (int*)(sm + SM_IDX);
    int* ends = starts + 128;

    const int tid = threadIdx.x;
    const int e0 = blockIdx.x * TE;
    const int tc = tid & 15;
    const int tr = tid >> 4;

    if (tid < 128) {
        starts[tid] = ei[e0 + tid];
        ends[tid]   = ei[NE + e0 + tid];
        Wis[tid]    = Wi[tid];
    }

    uint64_t acc[32];
#pragma unroll
    for (int i = 0; i < 32; i++) acc[i] = 0ull;

    // ---- GEMM1: h = silu(X @ We1 + be1), K = 272 (17 chunks) ----
    for (int kc = 0; kc < 17; kc++) {
        int k0 = kc * 16;
        __syncthreads();
        // gather X chunk (k-major into Xs)
#pragma unroll
        for (int it = 0; it < 2; it++) {
            int idx = tid + it * 256;   // 0..511
            int e = idx & 127;
            int q = idx >> 7;           // 0..3
            int kl = q * 4;
            int kg = k0 + kl;
            const float* src;
            if (kg < 128)      src = nf + (size_t)starts[e] * D + kg;
            else if (kg < 256) src = nf + (size_t)ends[e] * D + (kg - 128);
            else               src = ef + (size_t)(e0 + e) * DE + (kg - 256);
            float4 v = *(const float4*)src;
            Xs[(kl + 0) * 128 + e] = v.x;
            Xs[(kl + 1) * 128 + e] = v.y;
            Xs[(kl + 2) * 128 + e] = v.z;
            Xs[(kl + 3) * 128 + e] = v.w;
        }
        load_w_chunk(Ws, We1, k0, tid);
        __syncthreads();
        mma_chunk(Xs, 128, Ws, tr, tc, acc);
    }

    // epilogue 1: bias + silu, stage h^T into Hs[c][r]
    {
        float b[8];
#pragma unroll
        for (int j = 0; j < 8; j++)
            b[j] = be1[(j < 4) ? (tc * 4 + j) : (64 + tc * 4 + (j - 4))];
        __syncthreads();
#pragma unroll
        for (int i = 0; i < 8; i++) {
            int r = tr * 8 + i;
#pragma unroll
            for (int jp = 0; jp < 4; jp++) {
                float lo, hi;
                unpack2(acc[i * 4 + jp], lo, hi);
                int c = col_base(tc, jp);
                Hs[(c + 0) * HS_STRIDE + r] = siluf(lo + b[2 * jp]);
                Hs[(c + 1) * HS_STRIDE + r] = siluf(hi + b[2 * jp + 1]);
            }
        }
    }

#pragma unroll
    for (int i = 0; i < 32; i++) acc[i] = 0ull;

    // ---- GEMM2: m = h @ We2 + be2, K = 128 (8 chunks) ----
    for (int kc = 0; kc < 8; kc++) {
        int k0 = kc * 16;
        __syncthreads();
        load_w_chunk(Ws, We2, k0, tid);
        __syncthreads();
        mma_chunk(Hs + k0 * HS_STRIDE, HS_STRIDE, Ws, tr, tc, acc);
    }

    // epilogue 2: bias, stage m^T into Hs[c][r] (overwrite h)
    {
        float b[8];
#pragma unroll
        for (int j = 0; j < 8; j++)
            b[j] = be2[(j < 4) ? (tc * 4 + j) : (64 + tc * 4 + (j - 4))];
        __syncthreads();  // everyone done reading Hs
#pragma unroll
        for (int i = 0; i < 8; i++) {
            int r = tr * 8 + i;
#pragma unroll
            for (int jp = 0; jp < 4; jp++) {
                float lo, hi;
                unpack2(acc[i * 4 + jp], lo, hi);
                int c = col_base(tc, jp);
                Hs[(c + 0) * HS_STRIDE + r] = lo + b[2 * jp];
                Hs[(c + 1) * HS_STRIDE + r] = hi + b[2 * jp + 1];
            }
        }
    }
    __syncthreads();

    // gate: sigmoid(m . Wi + bi), one thread per edge row
    if (tid < 128) {
        float s = 0.0f;
#pragma unroll 8
        for (int c = 0; c < 128; c++) s += Hs[c * HS_STRIDE + tid] * Wis[c];
        gates[tid] = sigmoidf_(s + bi[0]);
    }
    __syncthreads();

    // gated atomic scatter: agg[start[r], :] += m[r, :] * gate[r]
    {
        int r = tid & 127;
        int cbase = (tid >> 7) * 64;
        float g = gates[r];
        float* dst = agg + (size_t)starts[r] * DM + cbase;
#pragma unroll 8
        for (int c = 0; c < 64; c++) {
            atomicAdd(dst + c, Hs[(cbase + c) * HS_STRIDE + r] * g);
        }
    }
}

// ---------------------------------------------------------------------------
// Node kernel: y=[nf|agg] -> silu(y@Wn1+bn1)@Wn2+bn2 + residual
// ---------------------------------------------------------------------------
__global__ void __launch_bounds__(256, 2)
node_kernel(const float* __restrict__ nf, const float* __restrict__ agg,
            const float* __restrict__ Wn1, const float* __restrict__ bn1,
            const float* __restrict__ Wn2, const float* __restrict__ bn2,
            float* __restrict__ out) {
    extern __shared__ float sm[];
    float* Xs = sm + SM_XS;
    float* Ws = sm + SM_WS;
    float* Hs = sm + SM_HS;

    const int tid = threadIdx.x;
    const int n0 = blockIdx.x * TE;
    const int tc = tid & 15;
    const int tr = tid >> 4;

    uint64_t acc[32];
#pragma unroll
    for (int i = 0; i < 32; i++) acc[i] = 0ull;

    // ---- GEMM1: K = 256 (16 chunks) ----
    for (int kc = 0; kc < 16; kc++) {
        int k0 = kc * 16;
        __syncthreads();
#pragma unroll
        for (int it = 0; it < 2; it++) {
            int idx = tid + it * 256;
            int e = idx & 127;
            int q = idx >> 7;
            int kl = q * 4;
            int kg = k0 + kl;
            int n = n0 + e;
            if (n >= NN) n = NN - 1;
            const float* src = (kg < 128) ? (nf + (size_t)n * D + kg)
                                          : (agg + (size_t)n * DM + (kg - 128));
            float4 v = *(const float4*)src;
            Xs[(kl + 0) * 128 + e] = v.x;
            Xs[(kl + 1) * 128 + e] = v.y;
            Xs[(kl + 2) * 128 + e] = v.z;
            Xs[(kl + 3) * 128 + e] = v.w;
        }
        load_w_chunk(Ws, Wn1, k0, tid);
        __syncthreads();
        mma_chunk(Xs, 128, Ws, tr, tc, acc);
    }

    // epilogue: silu, stage into Hs[c][r]
    {
        float b[8];
#pragma unroll
        for (int j = 0; j < 8; j++)
            b[j] = bn1[(j < 4) ? (tc * 4 + j) : (64 + tc * 4 + (j - 4))];
        __syncthreads();
#pragma unroll
        for (int i = 0; i < 8; i++) {
            int r = tr * 8 + i;
#pragma unroll
            for (int jp = 0; jp < 4; jp++) {
                float lo, hi;
                unpack2(acc[i * 4 + jp], lo, hi);
                int c = col_base(tc, jp);
                Hs[(c + 0) * HS_STRIDE + r] = siluf(lo + b[2 * jp]);
                Hs[(c + 1) * HS_STRIDE + r] = siluf(hi + b[2 * jp + 1]);
            }
        }
    }

#pragma unroll
    for (int i = 0; i < 32; i++) acc[i] = 0ull;

    // ---- GEMM2: K = 128 (8 chunks) ----
    for (int kc = 0; kc < 8; kc++) {
        int k0 = kc * 16;
        __syncthreads();
        load_w_chunk(Ws, Wn2, k0, tid);
        __syncthreads();
        mma_chunk(Hs + k0 * HS_STRIDE, HS_STRIDE, Ws, tr, tc, acc);
    }

    // epilogue: bias + residual, write out
    {
        float b[8];
#pragma unroll
        for (int j = 0; j < 8; j++)
            b[j] = bn2[(j < 4) ? (tc * 4 + j) : (64 + tc * 4 + (j - 4))];
#pragma unroll
        for (int i = 0; i < 8; i++) {
            int r = tr * 8 + i;
            int n = n0 + r;
            if (n >= NN) continue;
#pragma unroll
            for (int jp = 0; jp < 4; jp++) {
                float lo, hi;
                unpack2(acc[i * 4 + jp], lo, hi);
                int c = col_base(tc, jp);
                float2 res = *(const float2*)(nf + (size_t)n * D + c);
                float2 o;
                o.x = res.x + lo + b[2 * jp];
                o.y = res.y + hi + b[2 * jp + 1];
                *(float2*)(out + (size_t)n * D + c) = o;
            }
        }
    }
}

// ---------------------------------------------------------------------------
// Passthrough: edge_indices must be VALUE-cast int -> float (output dtype is
// float32), not bit-copied.
// ---------------------------------------------------------------------------
__global__ void idx_to_float_kernel(const int* __restrict__ ei,
                                    float* __restrict__ out) {
    int i = blockIdx.x * blockDim.x + threadIdx.x;
    if (i < 2 * NE) out[i] = (float)ei[i];
}

// ---------------------------------------------------------------------------
extern "C" void kernel_launch(void* const* d_in, const int* in_sizes, int n_in,
                              void* d_out, int out_size) {
    const float* nf  = (const float*)d_in[0];
    const int*   ei  = (const int*)d_in[1];
    const float* ef  = (const float*)d_in[2];
    const float* We1 = (const float*)d_in[3];
    const float* be1 = (const float*)d_in[4];
    const float* We2 = (const float*)d_in[5];
    const float* be2 = (const float*)d_in[6];
    const float* Wi  = (const float*)d_in[7];
    const float* bi  = (const float*)d_in[8];
    const float* Wn1 = (const float*)d_in[9];
    const float* bn1 = (const float*)d_in[10];
    const float* Wn2 = (const float*)d_in[11];
    const float* bn2 = (const float*)d_in[12];
    float* out = (float*)d_out;

    cudaFuncSetAttribute(edge_kernel, cudaFuncAttributeMaxDynamicSharedMemorySize, SMEM_BYTES);
    cudaFuncSetAttribute(node_kernel, cudaFuncAttributeMaxDynamicSharedMemorySize, SMEM_BYTES);

    void* aggp = nullptr;
    cudaGetSymbolAddress(&aggp, g_agg);
    cudaMemsetAsync(aggp, 0, (size_t)NN * DM * sizeof(float));

    edge_kernel<<<NE / TE, 256, SMEM_BYTES>>>(nf, ei, ef, We1, be1, We2, be2,
                                              Wi, bi, (float*)aggp);
    node_kernel<<<(NN + TE - 1) / TE, 256, SMEM_BYTES>>>(nf, (const float*)aggp,
                                                         Wn1, bn1, Wn2, bn2, out);

    // passthrough outputs: edge_indices (value-cast to float), then edge_features
    idx_to_float_kernel<<<(2 * NE + 255) / 256, 256>>>(ei, out + (size_t)NN * D);
    cudaMemcpyAsync(out + (size_t)NN * D + 2ull * NE, d_in[2],
                    (size_t)NE * DE * sizeof(float), cudaMemcpyDeviceToDevice);
}

// round 5
// speedup vs baseline: 2.4772x; 2.1484x over previous
#include <cuda_runtime.h>
#include <cstdint>

// Problem constants
#define NN 50000
#define NE 800000
#define D  128
#define DE 16
#define DM 128

// ---------------------------------------------------------------------------
// Global scratch
// ---------------------------------------------------------------------------
__device__ float g_agg[NN * DM];
// fragment-packed tf32 weights: [kc][nb][lane] float2 = (W[kc*8+t][n], W[kc*8+t+4][n])
__device__ float g_w1t[36 * 16 * 32 * 2];   // We1, K padded 272->288
__device__ float g_w2t[16 * 16 * 32 * 2];   // We2, K=128

// ---------------------------------------------------------------------------
// helpers
// ---------------------------------------------------------------------------
__device__ __forceinline__ float siluf(float x) { return x / (1.0f + __expf(-x)); }
__device__ __forceinline__ float sigmoidf_(float x) { return 1.0f / (1.0f + __expf(-x)); }

__device__ __forceinline__ uint32_t f2tf32(float f) {
    uint32_t u; asm("cvt.rna.tf32.f32 %0, %1;" : "=r"(u) : "f"(f)); return u;
}
__device__ __forceinline__ void mma_tf32(float c[4], const uint32_t a[4],
                                         uint32_t b0, uint32_t b1) {
    asm volatile("mma.sync.aligned.m16n8k8.row.col.f32.tf32.tf32.f32 "
        "{%0,%1,%2,%3}, {%4,%5,%6,%7}, {%8,%9}, {%0,%1,%2,%3};"
        : "+f"(c[0]), "+f"(c[1]), "+f"(c[2]), "+f"(c[3])
        : "r"(a[0]), "r"(a[1]), "r"(a[2]), "r"(a[3]), "r"(b0), "r"(b1));
}
__device__ __forceinline__ void red_add_v4(float* p, float a, float b, float c, float d) {
    asm volatile("red.global.add.v4.f32 [%0], {%1, %2, %3, %4};"
                 :: "l"(p), "f"(a), "f"(b), "f"(c), "f"(d) : "memory");
}

// ---------------------------------------------------------------------------
// Edge kernel SMEM layout (bytes)
//   hbuf : [128][132] f32  (h during GEMM2, then m-tile)         67584
//   Abuf : [128][36]  tf32 gathered X chunk                      18432
//   Bbuf : [4 kc][16 nb][32 lane] float2 fragment-packed chunk   16384
// ---------------------------------------------------------------------------
#define E_HBUF   0
#define E_ABUF   67584
#define E_BBUF   86016
#define E_STARTS 102400
#define E_ENDS   102912
#define E_BE1    103424
#define E_BE2    103936
#define E_WIS    104448
#define E_GATES  104960
#define E_SMEM_BYTES 105472

// ---------------------------------------------------------------------------
// Edge kernel: gather -> tf32 mma.sync MLP -> gate -> gated v4 red scatter
// ---------------------------------------------------------------------------
__global__ void __launch_bounds__(256, 2)
edge_kernel(const float* __restrict__ nf, const int* __restrict__ ei,
            const float* __restrict__ ef,
            const float* __restrict__ be1, const float* __restrict__ be2,
            const float* __restrict__ Wi, const float* __restrict__ bi,
            float* __restrict__ agg) {
    extern __shared__ char smem[];
    float* hbuf   = (float*)(smem + E_HBUF);      // stride 132
    uint32_t* Xs  = (uint32_t*)(smem + E_ABUF);   // stride 36
    const uint2* Bs = (const uint2*)(smem + E_BBUF);
    int*   starts = (int*)(smem + E_STARTS);
    int*   ends   = (int*)(smem + E_ENDS);
    float* be1s   = (float*)(smem + E_BE1);
    float* be2s   = (float*)(smem + E_BE2);
    float* wis    = (float*)(smem + E_WIS);
    float* gates  = (float*)(smem + E_GATES);

    const int tid  = threadIdx.x;
    const int lane = tid & 31;
    const int wid  = tid >> 5;
    const int wr   = wid & 3;        // row stripe: rows 32*wr .. +31
    const int wc   = wid >> 2;       // col half:   cols 64*wc .. +63
    const int g    = lane >> 2;      // group id (0..7)
    const int t    = lane & 3;       // thread-in-group (0..3)
    const int e0   = blockIdx.x * 128;

    if (tid < 128) {
        starts[tid] = ei[e0 + tid];
        ends[tid]   = ei[NE + e0 + tid];
        be1s[tid]   = be1[tid];
        be2s[tid]   = be2[tid];
        wis[tid]    = Wi[tid];
    }
    __syncthreads();

    float acc[2][8][4];
#pragma unroll
    for (int rg = 0; rg < 2; rg++)
#pragma unroll
        for (int nb = 0; nb < 8; nb++)
#pragma unroll
            for (int i = 0; i < 4; i++) acc[rg][nb][i] = 0.0f;

    // ================= GEMM1: D1 = X @ We1  (K=288 padded, 9 x 32) ==========
    for (int c = 0; c < 9; c++) {
        // --- stage A chunk (gather + tf32 cvt) ---
#pragma unroll
        for (int it = 0; it < 4; it++) {
            int seg = tid + it * 256;          // 0..1023
            int e = seg >> 3, s8 = seg & 7;    // row, 16B segment (4 floats)
            int k0 = c * 32;
            float4 v;
            if (c < 4)       v = *(const float4*)(nf + (size_t)starts[e] * D + k0 + s8 * 4);
            else if (c < 8)  v = *(const float4*)(nf + (size_t)ends[e] * D + (k0 - 128) + s8 * 4);
            else {
                if (s8 < 4)  v = *(const float4*)(ef + (size_t)(e0 + e) * DE + s8 * 4);
                else         v = make_float4(0.f, 0.f, 0.f, 0.f);
            }
            uint4 u = make_uint4(f2tf32(v.x), f2tf32(v.y), f2tf32(v.z), f2tf32(v.w));
            *(uint4*)(Xs + e * 36 + s8 * 4) = u;
        }
        // --- stage B chunk (fragment-packed copy, 16 KB) ---
        {
            const float4* src = (const float4*)(g_w1t + c * 4096);
            float4* dst = (float4*)(smem + E_BBUF);
#pragma unroll
            for (int it = 0; it < 4; it++) {
                int seg = tid + it * 256;
                dst[seg] = src[seg];
            }
        }
        __syncthreads();
        // --- MMA over 4 k-sub-chunks of 8 ---
#pragma unroll
        for (int kc = 0; kc < 4; kc++) {
            uint32_t a[2][4];
#pragma unroll
            for (int rg = 0; rg < 2; rg++) {
                const uint32_t* xb = Xs + (wr * 32 + rg * 16 + g) * 36 + kc * 8;
                a[rg][0] = xb[t];
                a[rg][1] = xb[8 * 36 + t];
                a[rg][2] = xb[t + 4];
                a[rg][3] = xb[8 * 36 + t + 4];
            }
#pragma unroll
            for (int nb = 0; nb < 8; nb++) {
                uint2 b = Bs[(kc * 16 + wc * 8 + nb) * 32 + lane];
                mma_tf32(acc[0][nb], a[0], b.x, b.y);
                mma_tf32(acc[1][nb], a[1], b.x, b.y);
            }
        }
        __syncthreads();
    }

    // ================= Epilogue 1: h = silu(D1 + be1) -> hbuf (tf32) ========
#pragma unroll
    for (int rg = 0; rg < 2; rg++) {
        int row0 = wr * 32 + rg * 16 + g;
#pragma unroll
        for (int nb = 0; nb < 8; nb++) {
            int col = wc * 64 + nb * 8 + 2 * t;
            float b0 = be1s[col], b1 = be1s[col + 1];
            uint2 h0 = make_uint2(f2tf32(siluf(acc[rg][nb][0] + b0)),
                                  f2tf32(siluf(acc[rg][nb][1] + b1)));
            uint2 h1 = make_uint2(f2tf32(siluf(acc[rg][nb][2] + b0)),
                                  f2tf32(siluf(acc[rg][nb][3] + b1)));
            *(uint2*)(hbuf + row0 * 132 + col) = h0;
            *(uint2*)(hbuf + (row0 + 8) * 132 + col) = h1;
            acc[rg][nb][0] = 0.f; acc[rg][nb][1] = 0.f;
            acc[rg][nb][2] = 0.f; acc[rg][nb][3] = 0.f;
        }
    }
    __syncthreads();

    // ================= GEMM2: D2 = h @ We2  (K=128, 4 x 32) =================
    const uint32_t* Hu = (const uint32_t*)hbuf;
    for (int c = 0; c < 4; c++) {
        {
            const float4* src = (const float4*)(g_w2t + c * 4096);
            float4* dst = (float4*)(smem + E_BBUF);
#pragma unroll
            for (int it = 0; it < 4; it++) {
                int seg = tid + it * 256;
                dst[seg] = src[seg];
            }
        }
        __syncthreads();
#pragma unroll
        for (int kc = 0; kc < 4; kc++) {
            uint32_t a[2][4];
#pragma unroll
            for (int rg = 0; rg < 2; rg++) {
                const uint32_t* xb = Hu + (wr * 32 + rg * 16 + g) * 132 + c * 32 + kc * 8;
                a[rg][0] = xb[t];
                a[rg][1] = xb[8 * 132 + t];
                a[rg][2] = xb[t + 4];
                a[rg][3] = xb[8 * 132 + t + 4];
            }
#pragma unroll
            for (int nb = 0; nb < 8; nb++) {
                uint2 b = Bs[(kc * 16 + wc * 8 + nb) * 32 + lane];
                mma_tf32(acc[0][nb], a[0], b.x, b.y);
                mma_tf32(acc[1][nb], a[1], b.x, b.y);
            }
        }
        __syncthreads();
    }

    // ================= Epilogue 2: m = D2 + be2 -> hbuf (f32 m-tile) ========
#pragma unroll
    for (int rg = 0; rg < 2; rg++) {
        int row0 = wr * 32 + rg * 16 + g;
#pragma unroll
        for (int nb = 0; nb < 8; nb++) {
            int col = wc * 64 + nb * 8 + 2 * t;
            float b0 = be2s[col], b1 = be2s[col + 1];
            *(float2*)(hbuf + row0 * 132 + col) =
                make_float2(acc[rg][nb][0] + b0, acc[rg][nb][1] + b1);
            *(float2*)(hbuf + (row0 + 8) * 132 + col) =
                make_float2(acc[rg][nb][2] + b0, acc[rg][nb][3] + b1);
        }
    }
    __syncthreads();

    // gate: sigmoid(m . Wi + bi)
    if (tid < 128) {
        float s = 0.0f;
#pragma unroll 8
        for (int c = 0; c < 128; c++) s += hbuf[tid * 132 + c] * wis[c];
        gates[tid] = sigmoidf_(s + bi[0]);
    }
    __syncthreads();

    // gated scatter: agg[start[r], :] += m[r, :] * gate[r]
    {
        const int r = tid & 127;
        const int cb = (tid >> 7) * 64;
        const float gt = gates[r];
        float* dst = agg + (size_t)starts[r] * DM + cb;
        const float* src = hbuf + r * 132 + cb;
#pragma unroll
        for (int c = 0; c < 64; c += 4) {
            float4 v = *(const float4*)(src + c);
            red_add_v4(dst + c, v.x * gt, v.y * gt, v.z * gt, v.w * gt);
        }
    }
}

// ---------------------------------------------------------------------------
// Weight prep: pack We1/We2 into mma fragment layout (tf32), K1 padded to 288
// ---------------------------------------------------------------------------
__global__ void prep_kernel(const float* __restrict__ We1,
                            const float* __restrict__ We2) {
    int i = blockIdx.x * 256 + threadIdx.x;
    if (i < 36 * 16 * 32) {
        int lane = i & 31;
        int nb = (i >> 5) & 15;
        int kc = i >> 9;
        int k = kc * 8 + (lane & 3);
        int n = nb * 8 + (lane >> 2);
        float v0 = (k < 272) ? We1[(size_t)k * 128 + n] : 0.0f;
        float v1 = (k + 4 < 272) ? We1[(size_t)(k + 4) * 128 + n] : 0.0f;
        ((uint2*)g_w1t)[i] = make_uint2(f2tf32(v0), f2tf32(v1));
    } else if (i < 36 * 16 * 32 + 16 * 16 * 32) {
        int j = i - 36 * 16 * 32;
        int lane = j & 31;
        int nb = (j >> 5) & 15;
        int kc = j >> 9;
        int k = kc * 8 + (lane & 3);
        int n = nb * 8 + (lane >> 2);
        float v0 = We2[(size_t)k * 128 + n];
        float v1 = We2[(size_t)(k + 4) * 128 + n];
        ((uint2*)g_w2t)[j] = make_uint2(f2tf32(v0), f2tf32(v1));
    }
}

// ===========================================================================
// Node kernel (SIMT f32x2 path — passed in R3, ~7% of runtime)
// ===========================================================================
#define HS_STRIDE 132
#define SM_XS   0
#define SM_WS   (16*128)
#define SM_HS   (2*16*128)
#define SMEM_FLOATS_NODE (SM_HS + 128*HS_STRIDE)
#define NODE_SMEM_BYTES (SMEM_FLOATS_NODE * 4)

__device__ __forceinline__ uint64_t pack2(float lo, float hi) {
    uint64_t r; asm("mov.b64 %0, {%1, %2};" : "=l"(r) : "f"(lo), "f"(hi)); return r;
}
__device__ __forceinline__ void unpack2(uint64_t v, float& lo, float& hi) {
    asm("mov.b64 {%0, %1}, %2;" : "=f"(lo), "=f"(hi) : "l"(v));
}
__device__ __forceinline__ void ffma2(uint64_t& d, uint64_t a, uint64_t b) {
    asm("fma.rn.f32x2 %0, %1, %2, %0;" : "+l"(d) : "l"(a), "l"(b));
}

__device__ __forceinline__ void mma_chunk(const float* __restrict__ Xsrc, int xstride,
                                          const float* __restrict__ Ws,
                                          int tr, int tc, uint64_t acc[32]) {
#pragma unroll
    for (int k = 0; k < 16; k++) {
        const float* xrow = Xsrc + k * xstride + tr * 8;
        float4 a0 = *(const float4*)(xrow);
        float4 a1 = *(const float4*)(xrow + 4);
        const float* wrow = Ws + k * 128 + tc * 4;
        ulonglong2 w0 = *(const ulonglong2*)(wrow);
        ulonglong2 w1 = *(const ulonglong2*)(wrow + 64);
        uint64_t b0 = w0.x, b1 = w0.y, b2 = w1.x, b3 = w1.y;
        float av[8] = {a0.x, a0.y, a0.z, a0.w, a1.x, a1.y, a1.z, a1.w};
#pragma unroll
        for (int i = 0; i < 8; i++) {
            uint64_t ap = pack2(av[i], av[i]);
            ffma2(acc[i * 4 + 0], ap, b0);
            ffma2(acc[i * 4 + 1], ap, b1);
            ffma2(acc[i * 4 + 2], ap, b2);
            ffma2(acc[i * 4 + 3], ap, b3);
        }
    }
}
__device__ __forceinline__ int col_base(int tc, int jp) {
    return (jp < 2) ? (tc * 4 + jp * 2) : (64 + tc * 4 + (jp - 2) * 2);
}
__device__ __forceinline__ void load_w_chunk(float* __restrict__ Ws,
                                             const float* __restrict__ W,
                                             int k0, int tid) {
#pragma unroll
    for (int it = 0; it < 2; it++) {
        int idx = tid + it * 256;
        int k = idx >> 5;
        int j = (idx & 31) * 4;
        float4 v = *(const float4*)(W + (size_t)(k0 + k) * 128 + j);
        *(float4*)(Ws + k * 128 + j) = v;
    }
}

__global__ void __launch_bounds__(256, 2)
node_kernel(const float* __restrict__ nf, const float* __restrict__ agg,
            const float* __restrict__ Wn1, const float* __restrict__ bn1,
            const float* __restrict__ Wn2, const float* __restrict__ bn2,
            float* __restrict__ out) {
    extern __shared__ float smf[];
    float* Xs = smf + SM_XS;
    float* Ws = smf + SM_WS;
    float* Hs = smf + SM_HS;

    const int tid = threadIdx.x;
    const int n0 = blockIdx.x * 128;
    const int tc = tid & 15;
    const int tr = tid >> 4;

    uint64_t acc[32];
#pragma unroll
    for (int i = 0; i < 32; i++) acc[i] = 0ull;

    for (int kc = 0; kc < 16; kc++) {
        int k0 = kc * 16;
        __syncthreads();
#pragma unroll
        for (int it = 0; it < 2; it++) {
            int idx = tid + it * 256;
            int e = idx & 127;
            int q = idx >> 7;
            int kl = q * 4;
            int kg = k0 + kl;
            int n = n0 + e;
            if (n >= NN) n = NN - 1;
            const float* src = (kg < 128) ? (nf + (size_t)n * D + kg)
                                          : (agg + (size_t)n * DM + (kg - 128));
            float4 v = *(const float4*)src;
            Xs[(kl + 0) * 128 + e] = v.x;
            Xs[(kl + 1) * 128 + e] = v.y;
            Xs[(kl + 2) * 128 + e] = v.z;
            Xs[(kl + 3) * 128 + e] = v.w;
        }
        load_w_chunk(Ws, Wn1, k0, tid);
        __syncthreads();
        mma_chunk(Xs, 128, Ws, tr, tc, acc);
    }
    {
        float b[8];
#pragma unroll
        for (int j = 0; j < 8; j++)
            b[j] = bn1[(j < 4) ? (tc * 4 + j) : (64 + tc * 4 + (j - 4))];
        __syncthreads();
#pragma unroll
        for (int i = 0; i < 8; i++) {
            int r = tr * 8 + i;
#pragma unroll
            for (int jp = 0; jp < 4; jp++) {
                float lo, hi;
                unpack2(acc[i * 4 + jp], lo, hi);
                int c = col_base(tc, jp);
                Hs[(c + 0) * HS_STRIDE + r] = siluf(lo + b[2 * jp]);
                Hs[(c + 1) * HS_STRIDE + r] = siluf(hi + b[2 * jp + 1]);
            }
        }
    }
#pragma unroll
    for (int i = 0; i < 32; i++) acc[i] = 0ull;
    for (int kc = 0; kc < 8; kc++) {
        int k0 = kc * 16;
        __syncthreads();
        load_w_chunk(Ws, Wn2, k0, tid);
        __syncthreads();
        mma_chunk(Hs + k0 * HS_STRIDE, HS_STRIDE, Ws, tr, tc, acc);
    }
    {
        float b[8];
#pragma unroll
        for (int j = 0; j < 8; j++)
            b[j] = bn2[(j < 4) ? (tc * 4 + j) : (64 + tc * 4 + (j - 4))];
#pragma unroll
        for (int i = 0; i < 8; i++) {
            int r = tr * 8 + i;
            int n = n0 + r;
            if (n >= NN) continue;
#pragma unroll
            for (int jp = 0; jp < 4; jp++) {
                float lo, hi;
                unpack2(acc[i * 4 + jp], lo, hi);
                int c = col_base(tc, jp);
                float2 res = *(const float2*)(nf + (size_t)n * D + c);
                float2 o;
                o.x = res.x + lo + b[2 * jp];
                o.y = res.y + hi + b[2 * jp + 1];
                *(float2*)(out + (size_t)n * D + c) = o;
            }
        }
    }
}

// ---------------------------------------------------------------------------
__global__ void idx_to_float_kernel(const int* __restrict__ ei,
                                    float* __restrict__ out) {
    int i = blockIdx.x * blockDim.x + threadIdx.x;
    if (i < 2 * NE) out[i] = (float)ei[i];
}

// ---------------------------------------------------------------------------
extern "C" void kernel_launch(void* const* d_in, const int* in_sizes, int n_in,
                              void* d_out, int out_size) {
    const float* nf  = (const float*)d_in[0];
    const int*   ei  = (const int*)d_in[1];
    const float* ef  = (const float*)d_in[2];
    const float* We1 = (const float*)d_in[3];
    const float* be1 = (const float*)d_in[4];
    const float* We2 = (const float*)d_in[5];
    const float* be2 = (const float*)d_in[6];
    const float* Wi  = (const float*)d_in[7];
    const float* bi  = (const float*)d_in[8];
    const float* Wn1 = (const float*)d_in[9];
    const float* bn1 = (const float*)d_in[10];
    const float* Wn2 = (const float*)d_in[11];
    const float* bn2 = (const float*)d_in[12];
    float* out = (float*)d_out;

    cudaFuncSetAttribute(edge_kernel, cudaFuncAttributeMaxDynamicSharedMemorySize, E_SMEM_BYTES);
    cudaFuncSetAttribute(node_kernel, cudaFuncAttributeMaxDynamicSharedMemorySize, NODE_SMEM_BYTES);

    void* aggp = nullptr;
    cudaGetSymbolAddress(&aggp, g_agg);
    cudaMemsetAsync(aggp, 0, (size_t)NN * DM * sizeof(float));

    prep_kernel<<<(36 * 16 * 32 + 16 * 16 * 32 + 255) / 256, 256>>>(We1, We2);

    edge_kernel<<<NE / 128, 256, E_SMEM_BYTES>>>(nf, ei, ef, be1, be2, Wi, bi,
                                                 (float*)aggp);
    node_kernel<<<(NN + 127) / 128, 256, NODE_SMEM_BYTES>>>(nf, (const float*)aggp,
                                                            Wn1, bn1, Wn2, bn2, out);

    idx_to_float_kernel<<<(2 * NE + 255) / 256, 256>>>(ei, out + (size_t)NN * D);
    cudaMemcpyAsync(out + (size_t)NN * D + 2ull * NE, d_in[2],
                    (size_t)NE * DE * sizeof(float), cudaMemcpyDeviceToDevice);
}

// round 6
// speedup vs baseline: 3.8362x; 1.5486x over previous
#include <cuda_runtime.h>
#include <cstdint>

#define NN 50000
#define NE 800000
#define D  128
#define DE 16
#define DM 128

// ---------------------------------------------------------------------------
// Global scratch
// ---------------------------------------------------------------------------
__device__ float g_agg[NN * DM];
// bf16 fragment-packed weights: entry = uint2{ b0, b1 } per (K16, nb, lane)
//   b0 = bf16x2( W[k0+2t][n], W[k0+2t+1][n] ),  b1 = same at k0+8
__device__ uint2 g_w1b[18 * 16 * 32];   // We1, K padded 272->288 (18 K16 blocks)
__device__ uint2 g_w2b[8 * 16 * 32];    // We2, K=128 (8 K16 blocks)

// ---------------------------------------------------------------------------
// helpers
// ---------------------------------------------------------------------------
__device__ __forceinline__ float siluf(float x) { return x / (1.0f + __expf(-x)); }
__device__ __forceinline__ float sigmoidf_(float x) { return 1.0f / (1.0f + __expf(-x)); }

__device__ __forceinline__ uint32_t bf2(float lo, float hi) {
    uint32_t r;
    asm("cvt.rn.bf16x2.f32 %0, %1, %2;" : "=r"(r) : "f"(hi), "f"(lo));
    return r;
}
__device__ __forceinline__ void mma_bf16(float c[4], const uint32_t a[4],
                                         uint32_t b0, uint32_t b1) {
    asm volatile("mma.sync.aligned.m16n8k16.row.col.f32.bf16.bf16.f32 "
        "{%0,%1,%2,%3}, {%4,%5,%6,%7}, {%8,%9}, {%0,%1,%2,%3};"
        : "+f"(c[0]), "+f"(c[1]), "+f"(c[2]), "+f"(c[3])
        : "r"(a[0]), "r"(a[1]), "r"(a[2]), "r"(a[3]), "r"(b0), "r"(b1));
}
__device__ __forceinline__ void red_add_v4(float* p, float a, float b, float c, float d) {
    asm volatile("red.global.add.v4.f32 [%0], {%1, %2, %3, %4};"
                 :: "l"(p), "f"(a), "f"(b), "f"(c), "f"(d) : "memory");
}

// ---------------------------------------------------------------------------
// Edge kernel SMEM layout (bytes)
//   hbuf: [128 rows][136 bf16] stride 272B (h tile, bf16)        34816
//   A0/A1: [128 rows][32 k bf16] stride 80B                      2x10240
//   B0/B1: [2 kcl][16 nb][32 lane] uint2                         2x8192
//   (GEMM2 stages all of g_w2b (32KB) over A0..B0;
//    m-tile f32 [128][132] = 67584B overlays hbuf+bufs at the end)
// ---------------------------------------------------------------------------
#define E_HBUF   0
#define E_A0     34816
#define E_A1     45056
#define E_B0     55296
#define E_B1     63488
#define E_MISC   71680
#define E_STARTS (E_MISC)
#define E_ENDS   (E_MISC + 512)
#define E_BE1    (E_MISC + 1024)
#define E_BE2    (E_MISC + 1536)
#define E_WIS    (E_MISC + 2048)
#define E_GATES  (E_MISC + 2560)
#define E_SMEM_BYTES (E_MISC + 3072)

// ---------------------------------------------------------------------------
// gather / staging helpers for GEMM1 pipeline
// ---------------------------------------------------------------------------
__device__ __forceinline__ void gather_A(int c, int tid, int e0,
                                         const int* starts, const int* ends,
                                         const float* __restrict__ nf,
                                         const float* __restrict__ ef,
                                         float4 va[4]) {
#pragma unroll
    for (int it = 0; it < 4; it++) {
        int seg = tid + it * 256;
        int e = seg >> 3, s8 = seg & 7;
        int k0 = c * 32;
        float4 v;
        if (c < 4)       v = *(const float4*)(nf + (size_t)starts[e] * D + k0 + s8 * 4);
        else if (c < 8)  v = *(const float4*)(nf + (size_t)ends[e] * D + (k0 - 128) + s8 * 4);
        else {
            if (s8 < 4)  v = *(const float4*)(ef + (size_t)(e0 + e) * DE + s8 * 4);
            else         v = make_float4(0.f, 0.f, 0.f, 0.f);
        }
        va[it] = v;
    }
}
__device__ __forceinline__ void store_A(char* Ab, int tid, const float4 va[4]) {
#pragma unroll
    for (int it = 0; it < 4; it++) {
        int seg = tid + it * 256;
        int e = seg >> 3, s8 = seg & 7;
        uint2 u = make_uint2(bf2(va[it].x, va[it].y), bf2(va[it].z, va[it].w));
        *(uint2*)(Ab + e * 80 + s8 * 8) = u;
    }
}

// ---------------------------------------------------------------------------
// Edge kernel: pipelined gather -> bf16 mma MLP -> gate -> gated v4 red scatter
// ---------------------------------------------------------------------------
__global__ void __launch_bounds__(256, 2)
edge_kernel(const float* __restrict__ nf, const int* __restrict__ ei,
            const float* __restrict__ ef,
            const float* __restrict__ be1, const float* __restrict__ be2,
            const float* __restrict__ Wi, const float* __restrict__ bi,
            float* __restrict__ agg) {
    extern __shared__ char smem[];
    float* mtile  = (float*)smem;                 // f32 [128][132] (late phase)
    char*  hbuf   = smem + E_HBUF;                // bf16, 272B row stride
    int*   starts = (int*)(smem + E_STARTS);
    int*   ends   = (int*)(smem + E_ENDS);
    float* be1s   = (float*)(smem + E_BE1);
    float* be2s   = (float*)(smem + E_BE2);
    float* wis    = (float*)(smem + E_WIS);
    float* gates  = (float*)(smem + E_GATES);

    const int tid  = threadIdx.x;
    const int lane = tid & 31;
    const int wid  = tid >> 5;
    const int wr   = wid & 3;        // row stripe
    const int wc   = wid >> 2;       // col half
    const int g    = lane >> 2;
    const int t    = lane & 3;
    const int e0   = blockIdx.x * 128;

    if (tid < 128) {
        starts[tid] = ei[e0 + tid];
        ends[tid]   = ei[NE + e0 + tid];
        be1s[tid]   = be1[tid];
        be2s[tid]   = be2[tid];
        wis[tid]    = Wi[tid];
    }
    __syncthreads();

    float acc[2][8][4];
#pragma unroll
    for (int rg = 0; rg < 2; rg++)
#pragma unroll
        for (int nb = 0; nb < 8; nb++)
#pragma unroll
            for (int i = 0; i < 4; i++) acc[rg][nb][i] = 0.0f;

    // ================= GEMM1: K=288 (9 chunks of 32), double-buffered ========
    {
        float4 va[4], vb[2];
        gather_A(0, tid, e0, starts, ends, nf, ef, va);
        const float4* w1 = (const float4*)g_w1b;
#pragma unroll
        for (int it = 0; it < 2; it++) vb[it] = w1[tid + it * 256];
        store_A(smem + E_A0, tid, va);
        {
            float4* dst = (float4*)(smem + E_B0);
#pragma unroll
            for (int it = 0; it < 2; it++) dst[tid + it * 256] = vb[it];
        }
        __syncthreads();

        for (int c = 0; c < 9; c++) {
            const int buf = c & 1;
            if (c < 8) {
                gather_A(c + 1, tid, e0, starts, ends, nf, ef, va);
#pragma unroll
                for (int it = 0; it < 2; it++)
                    vb[it] = w1[(c + 1) * 512 + tid + it * 256];
            }
            // --- MMA on buf ---
            const char* Ab = smem + (buf ? E_A1 : E_A0);
            const uint2* Bs = (const uint2*)(smem + (buf ? E_B1 : E_B0));
#pragma unroll
            for (int kcl = 0; kcl < 2; kcl++) {
                uint32_t a[2][4];
#pragma unroll
                for (int rg = 0; rg < 2; rg++) {
                    const char* p = Ab + (wr * 32 + rg * 16 + g) * 80 + kcl * 32 + t * 4;
                    a[rg][0] = *(const uint32_t*)p;
                    a[rg][1] = *(const uint32_t*)(p + 8 * 80);
                    a[rg][2] = *(const uint32_t*)(p + 16);
                    a[rg][3] = *(const uint32_t*)(p + 8 * 80 + 16);
                }
#pragma unroll
                for (int nb = 0; nb < 8; nb++) {
                    uint2 b = Bs[(kcl * 16 + wc * 8 + nb) * 32 + lane];
                    mma_bf16(acc[0][nb], a[0], b.x, b.y);
                    mma_bf16(acc[1][nb], a[1], b.x, b.y);
                }
            }
            __syncthreads();
            if (c < 8) {
                store_A(smem + ((c + 1) & 1 ? E_A1 : E_A0), tid, va);
                float4* dst = (float4*)(smem + ((c + 1) & 1 ? E_B1 : E_B0));
#pragma unroll
                for (int it = 0; it < 2; it++) dst[tid + it * 256] = vb[it];
                __syncthreads();
            }
        }
    }

    // ===== Epilogue 1: stage w2b (32KB) + h = silu(D1+be1) -> hbuf (bf16) ====
    {
        const float4* src = (const float4*)g_w2b;
        float4* dst = (float4*)(smem + E_A0);
#pragma unroll
        for (int it = 0; it < 8; it++) dst[tid + it * 256] = src[tid + it * 256];
    }
#pragma unroll
    for (int rg = 0; rg < 2; rg++) {
        int row0 = wr * 32 + rg * 16 + g;
#pragma unroll
        for (int nb = 0; nb < 8; nb++) {
            int col = wc * 64 + nb * 8 + 2 * t;
            float b0 = be1s[col], b1 = be1s[col + 1];
            uint32_t h0 = bf2(siluf(acc[rg][nb][0] + b0), siluf(acc[rg][nb][1] + b1));
            uint32_t h1 = bf2(siluf(acc[rg][nb][2] + b0), siluf(acc[rg][nb][3] + b1));
            *(uint32_t*)(hbuf + row0 * 272 + col * 2) = h0;
            *(uint32_t*)(hbuf + (row0 + 8) * 272 + col * 2) = h1;
            acc[rg][nb][0] = 0.f; acc[rg][nb][1] = 0.f;
            acc[rg][nb][2] = 0.f; acc[rg][nb][3] = 0.f;
        }
    }
    __syncthreads();

    // ================= GEMM2: D2 = h @ We2 (K=128, sync-free) ===============
    {
        const uint2* B2 = (const uint2*)(smem + E_A0);
#pragma unroll
        for (int K16 = 0; K16 < 8; K16++) {
            uint32_t a[2][4];
#pragma unroll
            for (int rg = 0; rg < 2; rg++) {
                const char* p = hbuf + (wr * 32 + rg * 16 + g) * 272 + K16 * 32 + t * 4;
                a[rg][0] = *(const uint32_t*)p;
                a[rg][1] = *(const uint32_t*)(p + 8 * 272);
                a[rg][2] = *(const uint32_t*)(p + 16);
                a[rg][3] = *(const uint32_t*)(p + 8 * 272 + 16);
            }
#pragma unroll
            for (int nb = 0; nb < 8; nb++) {
                uint2 b = B2[(K16 * 16 + wc * 8 + nb) * 32 + lane];
                mma_bf16(acc[0][nb], a[0], b.x, b.y);
                mma_bf16(acc[1][nb], a[1], b.x, b.y);
            }
        }
    }
    __syncthreads();   // all reads of hbuf/staging done before mtile overwrite

    // ===== Epilogue 2: m = D2 + be2 -> mtile (f32) ===========================
#pragma unroll
    for (int rg = 0; rg < 2; rg++) {
        int row0 = wr * 32 + rg * 16 + g;
#pragma unroll
        for (int nb = 0; nb < 8; nb++) {
            int col = wc * 64 + nb * 8 + 2 * t;
            float b0 = be2s[col], b1 = be2s[col + 1];
            *(float2*)(mtile + row0 * 132 + col) =
                make_float2(acc[rg][nb][0] + b0, acc[rg][nb][1] + b1);
            *(float2*)(mtile + (row0 + 8) * 132 + col) =
                make_float2(acc[rg][nb][2] + b0, acc[rg][nb][3] + b1);
        }
    }
    __syncthreads();

    // gate
    if (tid < 128) {
        float s = 0.0f;
#pragma unroll 8
        for (int c = 0; c < 128; c++) s += mtile[tid * 132 + c] * wis[c];
        gates[tid] = sigmoidf_(s + bi[0]);
    }
    __syncthreads();

    // gated scatter
    {
        const int r = tid & 127;
        const int cb = (tid >> 7) * 64;
        const float gt = gates[r];
        float* dst = agg + (size_t)starts[r] * DM + cb;
        const float* src = mtile + r * 132 + cb;
#pragma unroll
        for (int c = 0; c < 64; c += 4) {
            float4 v = *(const float4*)(src + c);
            red_add_v4(dst + c, v.x * gt, v.y * gt, v.z * gt, v.w * gt);
        }
    }
}

// ---------------------------------------------------------------------------
// Weight prep: pack We1/We2 into bf16 m16n8k16 fragment layout
// ---------------------------------------------------------------------------
__global__ void prep_kernel(const float* __restrict__ We1,
                            const float* __restrict__ We2) {
    int i = blockIdx.x * 256 + threadIdx.x;
    if (i < 18 * 16 * 32) {
        int lane = i & 31;
        int nbk = i >> 5;               // K16*16 + nb
        int k0 = (nbk >> 4) * 16;
        int n = (nbk & 15) * 8 + (lane >> 2);
        int t2 = (lane & 3) * 2;
        float v00 = (k0 + t2     < 272) ? We1[(size_t)(k0 + t2) * 128 + n] : 0.0f;
        float v01 = (k0 + t2 + 1 < 272) ? We1[(size_t)(k0 + t2 + 1) * 128 + n] : 0.0f;
        float v10 = (k0 + t2 + 8 < 272) ? We1[(size_t)(k0 + t2 + 8) * 128 + n] : 0.0f;
        float v11 = (k0 + t2 + 9 < 272) ? We1[(size_t)(k0 + t2 + 9) * 128 + n] : 0.0f;
        g_w1b[i] = make_uint2(bf2(v00, v01), bf2(v10, v11));
    } else if (i < 18 * 16 * 32 + 8 * 16 * 32) {
        int j = i - 18 * 16 * 32;
        int lane = j & 31;
        int nbk = j >> 5;
        int k0 = (nbk >> 4) * 16;
        int n = (nbk & 15) * 8 + (lane >> 2);
        int t2 = (lane & 3) * 2;
        float v00 = We2[(size_t)(k0 + t2) * 128 + n];
        float v01 = We2[(size_t)(k0 + t2 + 1) * 128 + n];
        float v10 = We2[(size_t)(k0 + t2 + 8) * 128 + n];
        float v11 = We2[(size_t)(k0 + t2 + 9) * 128 + n];
        g_w2b[j] = make_uint2(bf2(v00, v01), bf2(v10, v11));
    }
}

// ===========================================================================
// Node kernel (SIMT f32x2, fp32-exact — unchanged)
// ===========================================================================
#define HS_STRIDE 132
#define SM_XS   0
#define SM_WS   (16*128)
#define SM_HS   (2*16*128)
#define SMEM_FLOATS_NODE (SM_HS + 128*HS_STRIDE)
#define NODE_SMEM_BYTES (SMEM_FLOATS_NODE * 4)

__device__ __forceinline__ uint64_t pack2(float lo, float hi) {
    uint64_t r; asm("mov.b64 %0, {%1, %2};" : "=l"(r) : "f"(lo), "f"(hi)); return r;
}
__device__ __forceinline__ void unpack2(uint64_t v, float& lo, float& hi) {
    asm("mov.b64 {%0, %1}, %2;" : "=f"(lo), "=f"(hi) : "l"(v));
}
__device__ __forceinline__ void ffma2(uint64_t& d, uint64_t a, uint64_t b) {
    asm("fma.rn.f32x2 %0, %1, %2, %0;" : "+l"(d) : "l"(a), "l"(b));
}

__device__ __forceinline__ void mma_chunk(const float* __restrict__ Xsrc, int xstride,
                                          const float* __restrict__ Ws,
                                          int tr, int tc, uint64_t acc[32]) {
#pragma unroll
    for (int k = 0; k < 16; k++) {
        const float* xrow = Xsrc + k * xstride + tr * 8;
        float4 a0 = *(const float4*)(xrow);
        float4 a1 = *(const float4*)(xrow + 4);
        const float* wrow = Ws + k * 128 + tc * 4;
        ulonglong2 w0 = *(const ulonglong2*)(wrow);
        ulonglong2 w1 = *(const ulonglong2*)(wrow + 64);
        uint64_t b0 = w0.x, b1 = w0.y, b2 = w1.x, b3 = w1.y;
        float av[8] = {a0.x, a0.y, a0.z, a0.w, a1.x, a1.y, a1.z, a1.w};
#pragma unroll
        for (int i = 0; i < 8; i++) {
            uint64_t ap = pack2(av[i], av[i]);
            ffma2(acc[i * 4 + 0], ap, b0);
            ffma2(acc[i * 4 + 1], ap, b1);
            ffma2(acc[i * 4 + 2], ap, b2);
            ffma2(acc[i * 4 + 3], ap, b3);
        }
    }
}
__device__ __forceinline__ int col_base(int tc, int jp) {
    return (jp < 2) ? (tc * 4 + jp * 2) : (64 + tc * 4 + (jp - 2) * 2);
}
__device__ __forceinline__ void load_w_chunk(float* __restrict__ Ws,
                                             const float* __restrict__ W,
                                             int k0, int tid) {
#pragma unroll
    for (int it = 0; it < 2; it++) {
        int idx = tid + it * 256;
        int k = idx >> 5;
        int j = (idx & 31) * 4;
        float4 v = *(const float4*)(W + (size_t)(k0 + k) * 128 + j);
        *(float4*)(Ws + k * 128 + j) = v;
    }
}

__global__ void __launch_bounds__(256, 2)
node_kernel(const float* __restrict__ nf, const float* __restrict__ agg,
            const float* __restrict__ Wn1, const float* __restrict__ bn1,
            const float* __restrict__ Wn2, const float* __restrict__ bn2,
            float* __restrict__ out) {
    extern __shared__ float smf[];
    float* Xs = smf + SM_XS;
    float* Ws = smf + SM_WS;
    float* Hs = smf + SM_HS;

    const int tid = threadIdx.x;
    const int n0 = blockIdx.x * 128;
    const int tc = tid & 15;
    const int tr = tid >> 4;

    uint64_t acc[32];
#pragma unroll
    for (int i = 0; i < 32; i++) acc[i] = 0ull;

    for (int kc = 0; kc < 16; kc++) {
        int k0 = kc * 16;
        __syncthreads();
#pragma unroll
        for (int it = 0; it < 2; it++) {
            int idx = tid + it * 256;
            int e = idx & 127;
            int q = idx >> 7;
            int kl = q * 4;
            int kg = k0 + kl;
            int n = n0 + e;
            if (n >= NN) n = NN - 1;
            const float* src = (kg < 128) ? (nf + (size_t)n * D + kg)
                                          : (agg + (size_t)n * DM + (kg - 128));
            float4 v = *(const float4*)src;
            Xs[(kl + 0) * 128 + e] = v.x;
            Xs[(kl + 1) * 128 + e] = v.y;
            Xs[(kl + 2) * 128 + e] = v.z;
            Xs[(kl + 3) * 128 + e] = v.w;
        }
        load_w_chunk(Ws, Wn1, k0, tid);
        __syncthreads();
        mma_chunk(Xs, 128, Ws, tr, tc, acc);
    }
    {
        float b[8];
#pragma unroll
        for (int j = 0; j < 8; j++)
            b[j] = bn1[(j < 4) ? (tc * 4 + j) : (64 + tc * 4 + (j - 4))];
        __syncthreads();
#pragma unroll
        for (int i = 0; i < 8; i++) {
            int r = tr * 8 + i;
#pragma unroll
            for (int jp = 0; jp < 4; jp++) {
                float lo, hi;
                unpack2(acc[i * 4 + jp], lo, hi);
                int c = col_base(tc, jp);
                Hs[(c + 0) * HS_STRIDE + r] = siluf(lo + b[2 * jp]);
                Hs[(c + 1) * HS_STRIDE + r] = siluf(hi + b[2 * jp + 1]);
            }
        }
    }
#pragma unroll
    for (int i = 0; i < 32; i++) acc[i] = 0ull;
    for (int kc = 0; kc < 8; kc++) {
        int k0 = kc * 16;
        __syncthreads();
        load_w_chunk(Ws, Wn2, k0, tid);
        __syncthreads();
        mma_chunk(Hs + k0 * HS_STRIDE, HS_STRIDE, Ws, tr, tc, acc);
    }
    {
        float b[8];
#pragma unroll
        for (int j = 0; j < 8; j++)
            b[j] = bn2[(j < 4) ? (tc * 4 + j) : (64 + tc * 4 + (j - 4))];
#pragma unroll
        for (int i = 0; i < 8; i++) {
            int r = tr * 8 + i;
            int n = n0 + r;
            if (n >= NN) continue;
#pragma unroll
            for (int jp = 0; jp < 4; jp++) {
                float lo, hi;
                unpack2(acc[i * 4 + jp], lo, hi);
                int c = col_base(tc, jp);
                float2 res = *(const float2*)(nf + (size_t)n * D + c);
                float2 o;
                o.x = res.x + lo + b[2 * jp];
                o.y = res.y + hi + b[2 * jp + 1];
                *(float2*)(out + (size_t)n * D + c) = o;
            }
        }
    }
}

// ---------------------------------------------------------------------------
__global__ void idx_to_float_kernel(const int4* __restrict__ ei,
                                    float4* __restrict__ out) {
    int i = blockIdx.x * blockDim.x + threadIdx.x;
    if (i < (2 * NE) / 4) {
        int4 v = ei[i];
        out[i] = make_float4((float)v.x, (float)v.y, (float)v.z, (float)v.w);
    }
}

// ---------------------------------------------------------------------------
extern "C" void kernel_launch(void* const* d_in, const int* in_sizes, int n_in,
                              void* d_out, int out_size) {
    const float* nf  = (const float*)d_in[0];
    const int*   ei  = (const int*)d_in[1];
    const float* ef  = (const float*)d_in[2];
    const float* We1 = (const float*)d_in[3];
    const float* be1 = (const float*)d_in[4];
    const float* We2 = (const float*)d_in[5];
    const float* be2 = (const float*)d_in[6];
    const float* Wi  = (const float*)d_in[7];
    const float* bi  = (const float*)d_in[8];
    const float* Wn1 = (const float*)d_in[9];
    const float* bn1 = (const float*)d_in[10];
    const float* Wn2 = (const float*)d_in[11];
    const float* bn2 = (const float*)d_in[12];
    float* out = (float*)d_out;

    cudaFuncSetAttribute(edge_kernel, cudaFuncAttributeMaxDynamicSharedMemorySize, E_SMEM_BYTES);
    cudaFuncSetAttribute(node_kernel, cudaFuncAttributeMaxDynamicSharedMemorySize, NODE_SMEM_BYTES);

    void* aggp = nullptr;
    cudaGetSymbolAddress(&aggp, g_agg);
    cudaMemsetAsync(aggp, 0, (size_t)NN * DM * sizeof(float));

    prep_kernel<<<(18 * 16 * 32 + 8 * 16 * 32 + 255) / 256, 256>>>(We1, We2);

    edge_kernel<<<NE / 128, 256, E_SMEM_BYTES>>>(nf, ei, ef, be1, be2, Wi, bi,
                                                 (float*)aggp);
    node_kernel<<<(NN + 127) / 128, 256, NODE_SMEM_BYTES>>>(nf, (const float*)aggp,
                                                            Wn1, bn1, Wn2, bn2, out);

    idx_to_float_kernel<<<((2 * NE / 4) + 255) / 256, 256>>>(
        (const int4*)ei, (float4*)(out + (size_t)NN * D));
    cudaMemcpyAsync(out + (size_t)NN * D + 2ull * NE, d_in[2],
                    (size_t)NE * DE * sizeof(float), cudaMemcpyDeviceToDevice);
}